// round 2
// baseline (speedup 1.0000x reference)
#include <cuda_runtime.h>
#include <cuda_bf16.h>

// QuantumSubgenerator: 12-qubit RY / CNOT-ring / RY circuit + <Z_q> readout,
// reduced exactly via the Heisenberg picture to closed-form trig products.
//
//   alpha_q = latent[b][q] + w0[q]   (RY(a)RY(b)=RY(a+b) on |0>)
//   c_q = cos(alpha_q), s_q = sin(alpha_q), theta_q = w1[q]
//   out[b][0]  = cos(th_0) * prod_{r=1..11} c_r   - sin(th_0) * s_0*s_1
//   out[b][q]  = cos(th_q) * prod_{r=0..q}  c_r   - sin(th_q) * s_q*s_{q+1}   (1<=q<=10)
//   out[b][11] = cos(th_11)* prod_{r=0..11} c_r   - sin(th_11)* s_0*s_1*s_11
//
// Round 2: __sincosf (MUFU fast path; |angle| <~5 so abs err ~1e-6, fine vs
// 1e-3 threshold) + 32-thread blocks so 32 SMs share the latency instead of 8.

#define NQ 12

__global__ void __launch_bounds__(32)
QuantumSubgenerator_25314537242888_kernel(const float* __restrict__ latent,
                                          const float* __restrict__ weights,
                                          float* __restrict__ out, int B) {
    int b = blockIdx.x * blockDim.x + threadIdx.x;
    if (b >= B) return;

    // Vector-load this batch element's 12 latent angles (48B, 16B-aligned).
    const float4* lat4 = reinterpret_cast<const float4*>(latent + (size_t)b * NQ);
    float4 l0 = lat4[0], l1 = lat4[1], l2 = lat4[2];
    float lv[NQ] = {l0.x, l0.y, l0.z, l0.w,
                    l1.x, l1.y, l1.z, l1.w,
                    l2.x, l2.y, l2.z, l2.w};

    // Vector-load the 24 weights (w0 then w1).
    const float4* w4 = reinterpret_cast<const float4*>(weights);
    float4 w0a = __ldg(&w4[0]), w0b = __ldg(&w4[1]), w0c = __ldg(&w4[2]);
    float4 w1a = __ldg(&w4[3]), w1b = __ldg(&w4[4]), w1c = __ldg(&w4[5]);
    float w0v[NQ] = {w0a.x, w0a.y, w0a.z, w0a.w,
                     w0b.x, w0b.y, w0b.z, w0b.w,
                     w0c.x, w0c.y, w0c.z, w0c.w};
    float w1v[NQ] = {w1a.x, w1a.y, w1a.z, w1a.w,
                     w1b.x, w1b.y, w1b.z, w1b.w,
                     w1c.x, w1c.y, w1c.z, w1c.w};

    float c[NQ], s[NQ], cw[NQ], sw[NQ];
#pragma unroll
    for (int q = 0; q < NQ; q++) {
        __sincosf(lv[q] + w0v[q], &s[q], &c[q]);   // MUFU.SIN/COS
        __sincosf(w1v[q], &sw[q], &cw[q]);
    }

    float o[NQ];

    // out[0]: Z-string {1..11}, X-string {0,1}
    float p1to11 = 1.0f;
#pragma unroll
    for (int q = 1; q < NQ; q++) p1to11 *= c[q];
    o[0] = cw[0] * p1to11 - sw[0] * (s[0] * s[1]);

    // out[q] for q=1..10: Z-string {0..q}, X-string {q,q+1}
    float pref = c[0];
#pragma unroll
    for (int q = 1; q < NQ - 1; q++) {
        pref *= c[q];
        o[q] = cw[q] * pref - sw[q] * (s[q] * s[q + 1]);
    }

    // out[11]: Z-string {0..11}, X-string {0,1,11}
    pref *= c[NQ - 1];
    o[NQ - 1] = cw[NQ - 1] * pref - sw[NQ - 1] * (s[0] * s[1] * s[NQ - 1]);

    float4* out4 = reinterpret_cast<float4*>(out + (size_t)b * NQ);
    out4[0] = make_float4(o[0], o[1], o[2],  o[3]);
    out4[1] = make_float4(o[4], o[5], o[6],  o[7]);
    out4[2] = make_float4(o[8], o[9], o[10], o[11]);
}

extern "C" void kernel_launch(void* const* d_in, const int* in_sizes, int n_in,
                              void* d_out, int out_size) {
    const float* latent  = (const float*)d_in[0];
    const float* weights = (const float*)d_in[1];
    int lat_sz = in_sizes[0];
    // Robust to input-order surprises: weights tensor has exactly 2*NQ elems.
    if (n_in >= 2 && in_sizes[0] == 2 * NQ) {
        latent  = (const float*)d_in[1];
        weights = (const float*)d_in[0];
        lat_sz  = in_sizes[1];
    }
    int B = lat_sz / NQ;
    int threads = 32;                    // 1 warp/block -> spread across 32 SMs
    int blocks  = (B + threads - 1) / threads;
    QuantumSubgenerator_25314537242888_kernel<<<blocks, threads>>>(
        latent, weights, (float*)d_out, B);
}

// round 3
// speedup vs baseline: 1.4145x; 1.4145x over previous
#include <cuda_runtime.h>
#include <cuda_bf16.h>

// QuantumSubgenerator: 12-qubit RY / CNOT-ring / RY circuit + <Z_q> readout,
// reduced exactly (Heisenberg picture) to closed-form trig products:
//
//   alpha_q = latent[b][q] + w0[q];  c_q=cos(alpha_q), s_q=sin(alpha_q)
//   out[b][0]  = cos(th_0) * prod_{1..11} c_r  - sin(th_0)*s_0*s_1
//   out[b][q]  = cos(th_q) * prod_{0..q}  c_r  - sin(th_q)*s_q*s_{q+1}  (1<=q<=10)
//   out[b][11] = cos(th_11)* prod_{0..11} c_r  - sin(th_11)*s_0*s_1*s_11
//
// Round 3: lane-parallel. 16 lanes per batch element (lanes 0..11 active),
// 2 elements per warp, 8 per 128-thread block, 128 blocks = one wave over
// ~all SMs. Each lane does 2 MUFU sincos; the cos prefix-product is a
// 4-step segmented shfl scan (width=16). Critical path ~250 cycles vs
// ~600 for the serial thread-per-element version.

#define NQ 12
#define FULL 0xFFFFFFFFu

__global__ void __launch_bounds__(128)
QuantumSubgenerator_25314537242888_kernel(const float* __restrict__ latent,
                                          const float* __restrict__ weights,
                                          float* __restrict__ out, int B) {
    int seg  = threadIdx.x >> 4;                 // which 16-lane segment in block
    int q    = threadIdx.x & 15;                 // lane within segment (qubit id)
    int b    = blockIdx.x * 8 + seg;             // batch element
    bool act = (q < NQ) && (b < B);

    // Per-lane trig: alpha_q = latent + w0_q ; theta_q = w1_q
    float c = 1.0f, s = 0.0f, cw = 1.0f, sw = 0.0f;
    if (act) {
        float a = latent[(size_t)b * NQ + q] + __ldg(&weights[q]);
        __sincosf(a, &s, &c);
        __sincosf(__ldg(&weights[NQ + q]), &sw, &cw);
    }

    // Inclusive prefix product over lanes 1..q of c (lane0 contributes 1):
    // P'_q = prod_{1..q} c_r.  Segmented width-16 scan, 4 steps.
    float cp = (q == 0) ? 1.0f : c;
    #pragma unroll
    for (int d = 1; d < 16; d <<= 1) {
        float v = __shfl_up_sync(FULL, cp, d, 16);
        if (q >= d) cp *= v;
    }

    // Broadcasts within the 16-lane segment.
    float c0   = __shfl_sync(FULL, c,  0, 16);
    float s0   = __shfl_sync(FULL, s,  0, 16);
    float s1   = __shfl_sync(FULL, s,  1, 16);
    float ptot = __shfl_sync(FULL, cp, NQ - 1, 16);   // prod_{1..11} c_r
    float snx  = __shfl_down_sync(FULL, s, 1, 16);    // s_{q+1}

    if (act) {
        float o;
        if (q == 0) {
            o = cw * ptot - sw * (s0 * s1);
        } else if (q == NQ - 1) {
            o = cw * (c0 * ptot) - sw * (s0 * s1 * s);
        } else {
            o = cw * (c0 * cp) - sw * (s * snx);
        }
        out[(size_t)b * NQ + q] = o;
    }
}

extern "C" void kernel_launch(void* const* d_in, const int* in_sizes, int n_in,
                              void* d_out, int out_size) {
    const float* latent  = (const float*)d_in[0];
    const float* weights = (const float*)d_in[1];
    int lat_sz = in_sizes[0];
    // Robust to input-order surprises: weights tensor has exactly 2*NQ elems.
    if (n_in >= 2 && in_sizes[0] == 2 * NQ) {
        latent  = (const float*)d_in[1];
        weights = (const float*)d_in[0];
        lat_sz  = in_sizes[1];
    }
    int B = lat_sz / NQ;                 // 1024
    int blocks = (B + 7) / 8;            // 8 elements per 128-thread block
    QuantumSubgenerator_25314537242888_kernel<<<blocks, 128>>>(
        latent, weights, (float*)d_out, B);
}